// round 1
// baseline (speedup 1.0000x reference)
#include <cuda_runtime.h>
#include <math_constants.h>

#define BB 8
#define NN 4096
#define CC 256
#define KK 32
#define DD 512

// static scratch (allocation-free rule)
__device__ float g_feat[(size_t)BB * NN * CC];          // 32 MB
__device__ float g_pos [(size_t)BB * NN * CC];          // 32 MB
__device__ float g_sim [(size_t)BB * NN * NN];          // 512 MB

// ---------------------------------------------------------------------------
// GEMM1: feat_pos = x @ W^T + bias  (M=32768, N=512, K=256), NT layout
// BM=BN=64, BK=16, 256 threads, 4x4 micro-tile
// ---------------------------------------------------------------------------
__global__ __launch_bounds__(256) void gemm1_kernel(
    const float* __restrict__ x, const float* __restrict__ W,
    const float* __restrict__ bias)
{
    __shared__ float As[16][64];
    __shared__ float Bs[16][64];

    const int bx = blockIdx.x;          // 0..7   (cols of feat_pos / 64)
    const int by = blockIdx.y;          // 0..511 (rows / 64)
    const int tid = threadIdx.x;
    const int tx = tid & 15, ty = tid >> 4;
    const int loadRow = tid >> 2;       // 0..63
    const int loadQuad = tid & 3;       // 0..3

    float acc[4][4] = {};

    for (int k0 = 0; k0 < CC; k0 += 16) {
        float4 a = *(const float4*)(x + (size_t)(by * 64 + loadRow) * CC + k0 + loadQuad * 4);
        float4 b = *(const float4*)(W + (size_t)(bx * 64 + loadRow) * CC + k0 + loadQuad * 4);
        As[loadQuad * 4 + 0][loadRow] = a.x;
        As[loadQuad * 4 + 1][loadRow] = a.y;
        As[loadQuad * 4 + 2][loadRow] = a.z;
        As[loadQuad * 4 + 3][loadRow] = a.w;
        Bs[loadQuad * 4 + 0][loadRow] = b.x;
        Bs[loadQuad * 4 + 1][loadRow] = b.y;
        Bs[loadQuad * 4 + 2][loadRow] = b.z;
        Bs[loadQuad * 4 + 3][loadRow] = b.w;
        __syncthreads();
        #pragma unroll
        for (int kk = 0; kk < 16; kk++) {
            float4 av = *(const float4*)&As[kk][ty * 4];
            float4 bv = *(const float4*)&Bs[kk][tx * 4];
            acc[0][0] += av.x * bv.x; acc[0][1] += av.x * bv.y;
            acc[0][2] += av.x * bv.z; acc[0][3] += av.x * bv.w;
            acc[1][0] += av.y * bv.x; acc[1][1] += av.y * bv.y;
            acc[1][2] += av.y * bv.z; acc[1][3] += av.y * bv.w;
            acc[2][0] += av.z * bv.x; acc[2][1] += av.z * bv.y;
            acc[2][2] += av.z * bv.z; acc[2][3] += av.z * bv.w;
            acc[3][0] += av.w * bv.x; acc[3][1] += av.w * bv.y;
            acc[3][2] += av.w * bv.z; acc[3][3] += av.w * bv.w;
        }
        __syncthreads();
    }

    #pragma unroll
    for (int i = 0; i < 4; i++) {
        int row = by * 64 + ty * 4 + i;
        #pragma unroll
        for (int j = 0; j < 4; j++) {
            int d = bx * 64 + tx * 4 + j;
            float v = acc[i][j] + bias[d];
            if (d < CC) g_feat[(size_t)row * CC + d] = v;
            else        g_pos [(size_t)row * CC + (d - CC)] = v;
        }
    }
}

// ---------------------------------------------------------------------------
// Normalize pos rows: pos /= max(||pos||, 1e-12)
// ---------------------------------------------------------------------------
__global__ __launch_bounds__(256) void norm_kernel()
{
    const int row = blockIdx.x;
    const int tid = threadIdx.x;
    float v = g_pos[(size_t)row * CC + tid];
    float s = v * v;
    #pragma unroll
    for (int o = 16; o; o >>= 1) s += __shfl_down_sync(0xffffffffu, s, o);
    __shared__ float red[8];
    if ((tid & 31) == 0) red[tid >> 5] = s;
    __syncthreads();
    float total = red[0] + red[1] + red[2] + red[3] + red[4] + red[5] + red[6] + red[7];
    float scale = 1.0f / fmaxf(sqrtf(total), 1e-12f);
    g_pos[(size_t)row * CC + tid] = v * scale;
}

// ---------------------------------------------------------------------------
// GEMM2: sim_b = pos_b @ pos_b^T  (per batch, 4096x4096, K=256)
// ---------------------------------------------------------------------------
__global__ __launch_bounds__(256) void gemm2_kernel()
{
    __shared__ float As[16][64];
    __shared__ float Bs[16][64];

    const int b = blockIdx.z;
    const float* __restrict__ P = g_pos + (size_t)b * NN * CC;
    float* __restrict__ S = g_sim + (size_t)b * NN * NN;

    const int bx = blockIdx.x;          // cols/64
    const int by = blockIdx.y;          // rows/64
    const int tid = threadIdx.x;
    const int tx = tid & 15, ty = tid >> 4;
    const int loadRow = tid >> 2;
    const int loadQuad = tid & 3;

    float acc[4][4] = {};

    for (int k0 = 0; k0 < CC; k0 += 16) {
        float4 a = *(const float4*)(P + (size_t)(by * 64 + loadRow) * CC + k0 + loadQuad * 4);
        float4 bq = *(const float4*)(P + (size_t)(bx * 64 + loadRow) * CC + k0 + loadQuad * 4);
        As[loadQuad * 4 + 0][loadRow] = a.x;
        As[loadQuad * 4 + 1][loadRow] = a.y;
        As[loadQuad * 4 + 2][loadRow] = a.z;
        As[loadQuad * 4 + 3][loadRow] = a.w;
        Bs[loadQuad * 4 + 0][loadRow] = bq.x;
        Bs[loadQuad * 4 + 1][loadRow] = bq.y;
        Bs[loadQuad * 4 + 2][loadRow] = bq.z;
        Bs[loadQuad * 4 + 3][loadRow] = bq.w;
        __syncthreads();
        #pragma unroll
        for (int kk = 0; kk < 16; kk++) {
            float4 av = *(const float4*)&As[kk][ty * 4];
            float4 bv = *(const float4*)&Bs[kk][tx * 4];
            acc[0][0] += av.x * bv.x; acc[0][1] += av.x * bv.y;
            acc[0][2] += av.x * bv.z; acc[0][3] += av.x * bv.w;
            acc[1][0] += av.y * bv.x; acc[1][1] += av.y * bv.y;
            acc[1][2] += av.y * bv.z; acc[1][3] += av.y * bv.w;
            acc[2][0] += av.z * bv.x; acc[2][1] += av.z * bv.y;
            acc[2][2] += av.z * bv.z; acc[2][3] += av.z * bv.w;
            acc[3][0] += av.w * bv.x; acc[3][1] += av.w * bv.y;
            acc[3][2] += av.w * bv.z; acc[3][3] += av.w * bv.w;
        }
        __syncthreads();
    }

    #pragma unroll
    for (int i = 0; i < 4; i++) {
        int r = by * 64 + ty * 4 + i;
        #pragma unroll
        for (int j = 0; j < 4; j++) {
            int c = bx * 64 + tx * 4 + j;
            S[(size_t)r * NN + c] = acc[i][j];
        }
    }
}

// ---------------------------------------------------------------------------
// top-32 per sim row + softmax + gather feat + weighted sum
// one block (256 thr) per (b,n) row; each thread holds 16 candidates in regs
// ---------------------------------------------------------------------------
__global__ __launch_bounds__(256) void topk_kernel(float* __restrict__ out)
{
    const int row = blockIdx.x;               // b*NN + n
    const int b = row >> 12;
    const int tid = threadIdx.x;
    const float* __restrict__ srow = g_sim + (size_t)row * NN;

    float v[16];
    #pragma unroll
    for (int i = 0; i < 16; i++) v[i] = srow[tid + i * 256];

    __shared__ float topv[KK];
    __shared__ int   topi[KK];
    __shared__ unsigned long long s_red[8];
    __shared__ unsigned long long s_win;

    for (int it = 0; it < KK; it++) {
        float bv = v[0]; int bi = 0;
        #pragma unroll
        for (int i = 1; i < 16; i++) if (v[i] > bv) { bv = v[i]; bi = i; }
        unsigned key = __float_as_uint(bv);
        key = (key & 0x80000000u) ? ~key : (key | 0x80000000u);   // monotone map
        unsigned idx = (unsigned)(bi * 256 + tid);
        unsigned long long pk = ((unsigned long long)key << 32) | idx;
        #pragma unroll
        for (int o = 16; o; o >>= 1) {
            unsigned long long q = __shfl_down_sync(0xffffffffu, pk, o);
            if (q > pk) pk = q;
        }
        if ((tid & 31) == 0) s_red[tid >> 5] = pk;
        __syncthreads();
        if (tid == 0) {
            unsigned long long m = s_red[0];
            #pragma unroll
            for (int w = 1; w < 8; w++) if (s_red[w] > m) m = s_red[w];
            s_win = m;
            unsigned ukey = (unsigned)(m >> 32);
            ukey = (ukey & 0x80000000u) ? (ukey & 0x7fffffffu) : ~ukey;
            topv[it] = __uint_as_float(ukey);
            topi[it] = (int)(m & 0xffffffffu);
        }
        __syncthreads();
        unsigned widx = (unsigned)(s_win & 0xffffffffu);
        if ((int)(widx & 255u) == tid) v[widx >> 8] = -CUDART_INF_F;
    }

    // softmax over topv (topv[0] is the max — selected in descending order)
    __shared__ float attn[KK];
    if (tid < KK) attn[tid] = expf(topv[tid] - topv[0]);
    __syncthreads();
    float sum = 0.f;
    #pragma unroll
    for (int k = 0; k < KK; k++) sum += attn[k];
    float inv = 1.0f / sum;

    const size_t fbase = (size_t)b * NN * CC;
    float acc = 0.f;
    #pragma unroll 4
    for (int k = 0; k < KK; k++) {
        int id = topi[k];
        acc += attn[k] * g_feat[fbase + (size_t)id * CC + tid];
    }
    out[(size_t)row * CC + tid] = acc * inv;
}

// ---------------------------------------------------------------------------
extern "C" void kernel_launch(void* const* d_in, const int* in_sizes, int n_in,
                              void* d_out, int out_size)
{
    const float* x    = (const float*)d_in[0];
    const float* W    = (const float*)d_in[1];
    const float* bias = (const float*)d_in[2];
    float* out = (float*)d_out;

    dim3 g1(DD / 64, (BB * NN) / 64);
    gemm1_kernel<<<g1, 256>>>(x, W, bias);

    norm_kernel<<<BB * NN, 256>>>();

    dim3 g2(NN / 64, NN / 64, BB);
    gemm2_kernel<<<g2, 256>>>();

    topk_kernel<<<BB * NN, 256>>>(out);
}

// round 4
// speedup vs baseline: 1.3359x; 1.3359x over previous
#include <cuda_runtime.h>
#include <math_constants.h>

#define BB 8
#define NN 4096
#define CC 256
#define KK 32
#define DD 512

// static scratch (allocation-free rule)
__device__ float g_feat[(size_t)BB * NN * CC];          // 32 MB
__device__ float g_pos [(size_t)BB * NN * CC];          // 32 MB
__device__ float g_sim [(size_t)BB * NN * NN];          // 512 MB

// ---------------------------------------------------------------------------
// GEMM1: feat_pos = x @ W^T + bias  (M=32768, N=512, K=256), NT layout
// BM=BN=128, BK=16, 256 threads, 8x8 micro-tile
// ---------------------------------------------------------------------------
__global__ __launch_bounds__(256, 2) void gemm1_kernel(
    const float* __restrict__ x, const float* __restrict__ W,
    const float* __restrict__ bias)
{
    __shared__ float As[16][132];
    __shared__ float Bs[16][132];

    const int bx = blockIdx.x;          // 0..3   (cols / 128)
    const int by = blockIdx.y;          // 0..255 (rows / 128)
    const int tid = threadIdx.x;
    const int tx = tid & 15, ty = tid >> 4;
    const int lr = tid >> 1;            // 0..127
    const int lq = (tid & 1) * 2;       // 0 or 2 (quad pair)

    float acc[8][8] = {};

    const float* xrow = x + (size_t)(by * 128 + lr) * CC;
    const float* wrow = W + (size_t)(bx * 128 + lr) * CC;

    for (int k0 = 0; k0 < CC; k0 += 16) {
        float4 a0 = *(const float4*)(xrow + k0 + lq * 4);
        float4 a1 = *(const float4*)(xrow + k0 + lq * 4 + 4);
        float4 b0 = *(const float4*)(wrow + k0 + lq * 4);
        float4 b1 = *(const float4*)(wrow + k0 + lq * 4 + 4);
        As[lq * 4 + 0][lr] = a0.x; As[lq * 4 + 1][lr] = a0.y;
        As[lq * 4 + 2][lr] = a0.z; As[lq * 4 + 3][lr] = a0.w;
        As[lq * 4 + 4][lr] = a1.x; As[lq * 4 + 5][lr] = a1.y;
        As[lq * 4 + 6][lr] = a1.z; As[lq * 4 + 7][lr] = a1.w;
        Bs[lq * 4 + 0][lr] = b0.x; Bs[lq * 4 + 1][lr] = b0.y;
        Bs[lq * 4 + 2][lr] = b0.z; Bs[lq * 4 + 3][lr] = b0.w;
        Bs[lq * 4 + 4][lr] = b1.x; Bs[lq * 4 + 5][lr] = b1.y;
        Bs[lq * 4 + 6][lr] = b1.z; Bs[lq * 4 + 7][lr] = b1.w;
        __syncthreads();
        #pragma unroll
        for (int kk = 0; kk < 16; kk++) {
            float ar[8], br[8];
            *(float4*)&ar[0] = *(const float4*)&As[kk][ty * 8];
            *(float4*)&ar[4] = *(const float4*)&As[kk][ty * 8 + 4];
            *(float4*)&br[0] = *(const float4*)&Bs[kk][tx * 8];
            *(float4*)&br[4] = *(const float4*)&Bs[kk][tx * 8 + 4];
            #pragma unroll
            for (int i = 0; i < 8; i++)
                #pragma unroll
                for (int j = 0; j < 8; j++)
                    acc[i][j] += ar[i] * br[j];
        }
        __syncthreads();
    }

    // bias + split store; tile is entirely feat (bx<2) or pos (bx>=2)
    float* dst = (bx < 2) ? g_feat : g_pos;
    const int col0 = ((bx < 2) ? bx : (bx - 2)) * 128 + tx * 8;
    float bi[8];
    *(float4*)&bi[0] = *(const float4*)(bias + bx * 128 + tx * 8);
    *(float4*)&bi[4] = *(const float4*)(bias + bx * 128 + tx * 8 + 4);

    #pragma unroll
    for (int i = 0; i < 8; i++) {
        int r = by * 128 + ty * 8 + i;
        float4 v0, v1;
        v0.x = acc[i][0] + bi[0]; v0.y = acc[i][1] + bi[1];
        v0.z = acc[i][2] + bi[2]; v0.w = acc[i][3] + bi[3];
        v1.x = acc[i][4] + bi[4]; v1.y = acc[i][5] + bi[5];
        v1.z = acc[i][6] + bi[6]; v1.w = acc[i][7] + bi[7];
        *(float4*)(dst + (size_t)r * CC + col0)     = v0;
        *(float4*)(dst + (size_t)r * CC + col0 + 4) = v1;
    }
}

// ---------------------------------------------------------------------------
// Normalize pos rows: pos /= max(||pos||, 1e-12)
// ---------------------------------------------------------------------------
__global__ __launch_bounds__(256) void norm_kernel()
{
    const int row = blockIdx.x;
    const int tid = threadIdx.x;
    float v = g_pos[(size_t)row * CC + tid];
    float s = v * v;
    #pragma unroll
    for (int o = 16; o; o >>= 1) s += __shfl_down_sync(0xffffffffu, s, o);
    __shared__ float red[8];
    if ((tid & 31) == 0) red[tid >> 5] = s;
    __syncthreads();
    float total = red[0] + red[1] + red[2] + red[3] + red[4] + red[5] + red[6] + red[7];
    float scale = 1.0f / fmaxf(sqrtf(total), 1e-12f);
    g_pos[(size_t)row * CC + tid] = v * scale;
}

// ---------------------------------------------------------------------------
// GEMM2 (symmetric): sim_b = pos_b @ pos_b^T. Only tiles by<=bx computed;
// mirror written transposed. BM=BN=128, BK=16, 256 thr, 8x8 micro-tile.
// ---------------------------------------------------------------------------
__global__ __launch_bounds__(256, 2) void gemm2_sym_kernel()
{
    __shared__ float As[16][132];
    __shared__ float Bs[16][132];

    const int b = blockIdx.z;
    const float* __restrict__ P = g_pos + (size_t)b * NN * CC;
    float* __restrict__ S = g_sim + (size_t)b * NN * NN;

    // linear tile index -> (by, bx), by <= bx, NT = 32 tiles/dim
    const int NT = NN / 128;
    const int t = blockIdx.x;
    float ff = (float)((2 * NT + 1) * (2 * NT + 1)) - 8.0f * (float)t;
    int by = (int)floorf(((float)(2 * NT + 1) - sqrtf(ff)) * 0.5f);
    while ((by + 1) * NT - ((by + 1) * by) / 2 <= t) by++;
    while (by * NT - (by * (by - 1)) / 2 > t) by--;
    const int bx = by + (t - (by * NT - (by * (by - 1)) / 2));

    const int tid = threadIdx.x;
    const int tx = tid & 15, ty = tid >> 4;
    const int lr = tid >> 1;
    const int lq = (tid & 1) * 2;

    float acc[8][8] = {};

    const float* arow = P + (size_t)(by * 128 + lr) * CC;
    const float* brow = P + (size_t)(bx * 128 + lr) * CC;

    for (int k0 = 0; k0 < CC; k0 += 16) {
        float4 a0 = *(const float4*)(arow + k0 + lq * 4);
        float4 a1 = *(const float4*)(arow + k0 + lq * 4 + 4);
        float4 b0 = *(const float4*)(brow + k0 + lq * 4);
        float4 b1 = *(const float4*)(brow + k0 + lq * 4 + 4);
        As[lq * 4 + 0][lr] = a0.x; As[lq * 4 + 1][lr] = a0.y;
        As[lq * 4 + 2][lr] = a0.z; As[lq * 4 + 3][lr] = a0.w;
        As[lq * 4 + 4][lr] = a1.x; As[lq * 4 + 5][lr] = a1.y;
        As[lq * 4 + 6][lr] = a1.z; As[lq * 4 + 7][lr] = a1.w;
        Bs[lq * 4 + 0][lr] = b0.x; Bs[lq * 4 + 1][lr] = b0.y;
        Bs[lq * 4 + 2][lr] = b0.z; Bs[lq * 4 + 3][lr] = b0.w;
        Bs[lq * 4 + 4][lr] = b1.x; Bs[lq * 4 + 5][lr] = b1.y;
        Bs[lq * 4 + 6][lr] = b1.z; Bs[lq * 4 + 7][lr] = b1.w;
        __syncthreads();
        #pragma unroll
        for (int kk = 0; kk < 16; kk++) {
            float ar[8], br[8];
            *(float4*)&ar[0] = *(const float4*)&As[kk][ty * 8];
            *(float4*)&ar[4] = *(const float4*)&As[kk][ty * 8 + 4];
            *(float4*)&br[0] = *(const float4*)&Bs[kk][tx * 8];
            *(float4*)&br[4] = *(const float4*)&Bs[kk][tx * 8 + 4];
            #pragma unroll
            for (int i = 0; i < 8; i++)
                #pragma unroll
                for (int j = 0; j < 8; j++)
                    acc[i][j] += ar[i] * br[j];
        }
        __syncthreads();
    }

    // direct store
    #pragma unroll
    for (int i = 0; i < 8; i++) {
        int r = by * 128 + ty * 8 + i;
        int c = bx * 128 + tx * 8;
        *(float4*)(S + (size_t)r * NN + c)     = *(float4*)&acc[i][0];
        *(float4*)(S + (size_t)r * NN + c + 4) = *(float4*)&acc[i][4];
    }
    // mirror store (transposed), skip diagonal tiles
    if (bx != by) {
        #pragma unroll
        for (int j = 0; j < 8; j++) {
            int c = bx * 128 + tx * 8 + j;
            int rb = by * 128 + ty * 8;
            float4 t0, t1;
            t0.x = acc[0][j]; t0.y = acc[1][j]; t0.z = acc[2][j]; t0.w = acc[3][j];
            t1.x = acc[4][j]; t1.y = acc[5][j]; t1.z = acc[6][j]; t1.w = acc[7][j];
            *(float4*)(S + (size_t)c * NN + rb)     = t0;
            *(float4*)(S + (size_t)c * NN + rb + 4) = t1;
        }
    }
}

// ---------------------------------------------------------------------------
// top-32 per sim row + softmax + gather feat + weighted sum.
// Hierarchical: each warp -> local top-32 (barrier-free), warp 0 merges.
// Tie-break: lowest index (matches jax.lax.top_k) via ~idx in packed key.
// ---------------------------------------------------------------------------
__global__ __launch_bounds__(256) void topk_kernel(float* __restrict__ out)
{
    const int row = blockIdx.x;               // b*NN + n
    const int b = row >> 12;
    const int tid = threadIdx.x;
    const int lane = tid & 31, w = tid >> 5;
    const float* __restrict__ srow = g_sim + (size_t)row * NN;

    // 16 candidates/thread as packed (monotone_key << 32) | ~idx
    unsigned long long pk[16];
    #pragma unroll
    for (int i = 0; i < 4; i++) {
        int col = w * 512 + i * 128 + lane * 4;
        float4 f = *(const float4*)(srow + col);
        float fv[4] = {f.x, f.y, f.z, f.w};
        #pragma unroll
        for (int j = 0; j < 4; j++) {
            unsigned u = __float_as_uint(fv[j]);
            unsigned key = u ^ (0x80000000u | (unsigned)((int)u >> 31));
            pk[i * 4 + j] = ((unsigned long long)key << 32) | (unsigned)(~(col + j));
        }
    }

    __shared__ unsigned long long cand[8 * KK];
    __shared__ float topv[KK];
    __shared__ int   topi[KK];
    __shared__ float attn[KK];

    // warp-local top-32 (no block barriers)
    for (int it = 0; it < KK; it++) {
        unsigned long long m = pk[0];
        #pragma unroll
        for (int i = 1; i < 16; i++) m = (pk[i] > m) ? pk[i] : m;
        #pragma unroll
        for (int o = 16; o; o >>= 1) {
            unsigned long long q = __shfl_xor_sync(0xffffffffu, m, o);
            m = (q > m) ? q : m;
        }
        if (lane == 0) cand[w * KK + it] = m;
        // owner clears its slot
        int local = (int)(~(unsigned)m) - w * 512;
        if (local >= 0 && local < 512 && ((local >> 2) & 31) == lane)
            pk[(local >> 7) * 4 + (local & 3)] = 0ull;
    }
    __syncthreads();

    // warp 0 merges 256 candidates -> global top-32
    if (w == 0) {
        unsigned long long c[8];
        #pragma unroll
        for (int i = 0; i < 8; i++) c[i] = cand[lane + i * 32];
        for (int it = 0; it < KK; it++) {
            unsigned long long m = c[0];
            #pragma unroll
            for (int i = 1; i < 8; i++) m = (c[i] > m) ? c[i] : m;
            #pragma unroll
            for (int o = 16; o; o >>= 1) {
                unsigned long long q = __shfl_xor_sync(0xffffffffu, m, o);
                m = (q > m) ? q : m;
            }
            if (lane == 0) {
                unsigned ukey = (unsigned)(m >> 32);
                unsigned u = (ukey & 0x80000000u) ? (ukey ^ 0x80000000u) : ~ukey;
                topv[it] = __uint_as_float(u);
                topi[it] = (int)(~(unsigned)m);
            }
            #pragma unroll
            for (int i = 0; i < 8; i++) if (c[i] == m) c[i] = 0ull;
        }
    }
    __syncthreads();

    // softmax over topv (topv[0] is the max) + gather + weighted sum
    if (tid < KK) attn[tid] = expf(topv[tid] - topv[0]);
    __syncthreads();
    float sum = 0.f;
    #pragma unroll
    for (int k = 0; k < KK; k++) sum += attn[k];
    float inv = 1.0f / sum;

    const size_t fbase = (size_t)b * NN * CC;
    float acc = 0.f;
    #pragma unroll 4
    for (int k = 0; k < KK; k++) {
        int id = topi[k];
        acc += attn[k] * g_feat[fbase + (size_t)id * CC + tid];
    }
    out[(size_t)row * CC + tid] = acc * inv;
}

// ---------------------------------------------------------------------------
extern "C" void kernel_launch(void* const* d_in, const int* in_sizes, int n_in,
                              void* d_out, int out_size)
{
    const float* x    = (const float*)d_in[0];
    const float* W    = (const float*)d_in[1];
    const float* bias = (const float*)d_in[2];
    float* out = (float*)d_out;

    dim3 g1(DD / 128, (BB * NN) / 128);
    gemm1_kernel<<<g1, 256>>>(x, W, bias);

    norm_kernel<<<BB * NN, 256>>>();

    const int NT = NN / 128;
    dim3 g2(NT * (NT + 1) / 2, 1, BB);
    gemm2_sym_kernel<<<g2, 256>>>();

    topk_kernel<<<BB * NN, 256>>>(out);
}

// round 7
// speedup vs baseline: 2.3687x; 1.7731x over previous
#include <cuda_runtime.h>
#include <cuda_bf16.h>
#include <math_constants.h>
#include <cstdint>

#define BB 8
#define NN 4096
#define CC 256
#define KK 32
#define DD 512

// static scratch (allocation-free rule)
__device__ float g_feat[(size_t)BB * NN * CC];          // 32 MB
__device__ float g_pos [(size_t)BB * NN * CC];          // 32 MB
__device__ float g_sim [(size_t)BB * NN * NN];          // 512 MB
__device__ __nv_bfloat16 g_hi [(size_t)BB * NN * CC];   // 16 MB
__device__ __nv_bfloat16 g_mid[(size_t)BB * NN * CC];   // 16 MB
__device__ __nv_bfloat16 g_lo [(size_t)BB * NN * CC];   // 16 MB

static __device__ __forceinline__ uint32_t smem_u32(const void* p) {
    return (uint32_t)__cvta_generic_to_shared(p);
}
#define SMEM_SWIZZLE_128B(off) ((off) ^ (((off) >> 3) & 0x70))

static __device__ __forceinline__ void cp_async16(uint32_t dst, const void* src) {
    asm volatile("cp.async.cg.shared.global [%0], [%1], 16;" :: "r"(dst), "l"(src));
}
#define CP_COMMIT() asm volatile("cp.async.commit_group;" ::: "memory")
#define CP_WAIT(n)  asm volatile("cp.async.wait_group %0;" :: "n"(n) : "memory")

static __device__ __forceinline__ void ldm_x4(uint32_t* r, uint32_t addr) {
    asm volatile("ldmatrix.sync.aligned.m8n8.x4.shared.b16 {%0,%1,%2,%3}, [%4];"
                 : "=r"(r[0]), "=r"(r[1]), "=r"(r[2]), "=r"(r[3]) : "r"(addr));
}
static __device__ __forceinline__ void mma_bf16(
    float* c, const uint32_t* a, uint32_t b0, uint32_t b1) {
    asm volatile(
        "mma.sync.aligned.m16n8k16.row.col.f32.bf16.bf16.f32 "
        "{%0,%1,%2,%3}, {%4,%5,%6,%7}, {%8,%9}, {%0,%1,%2,%3};"
        : "+f"(c[0]), "+f"(c[1]), "+f"(c[2]), "+f"(c[3])
        : "r"(a[0]), "r"(a[1]), "r"(a[2]), "r"(a[3]), "r"(b0), "r"(b1));
}

// ===========================================================================
// GEMM1: feat_pos = x @ W^T + bias (M=32768, N=512, K=256), SIMT fp32
// ===========================================================================
__global__ __launch_bounds__(256, 2) void gemm1_kernel(
    const float* __restrict__ x, const float* __restrict__ W,
    const float* __restrict__ bias)
{
    __shared__ float As[16][132];
    __shared__ float Bs[16][132];

    const int bx = blockIdx.x, by = blockIdx.y;
    const int tid = threadIdx.x;
    const int tx = tid & 15, ty = tid >> 4;
    const int lr = tid >> 1;
    const int lq = (tid & 1) * 2;

    float acc[8][8] = {};
    const float* xrow = x + (size_t)(by * 128 + lr) * CC;
    const float* wrow = W + (size_t)(bx * 128 + lr) * CC;

    for (int k0 = 0; k0 < CC; k0 += 16) {
        float4 a0 = *(const float4*)(xrow + k0 + lq * 4);
        float4 a1 = *(const float4*)(xrow + k0 + lq * 4 + 4);
        float4 b0 = *(const float4*)(wrow + k0 + lq * 4);
        float4 b1 = *(const float4*)(wrow + k0 + lq * 4 + 4);
        As[lq * 4 + 0][lr] = a0.x; As[lq * 4 + 1][lr] = a0.y;
        As[lq * 4 + 2][lr] = a0.z; As[lq * 4 + 3][lr] = a0.w;
        As[lq * 4 + 4][lr] = a1.x; As[lq * 4 + 5][lr] = a1.y;
        As[lq * 4 + 6][lr] = a1.z; As[lq * 4 + 7][lr] = a1.w;
        Bs[lq * 4 + 0][lr] = b0.x; Bs[lq * 4 + 1][lr] = b0.y;
        Bs[lq * 4 + 2][lr] = b0.z; Bs[lq * 4 + 3][lr] = b0.w;
        Bs[lq * 4 + 4][lr] = b1.x; Bs[lq * 4 + 5][lr] = b1.y;
        Bs[lq * 4 + 6][lr] = b1.z; Bs[lq * 4 + 7][lr] = b1.w;
        __syncthreads();
        #pragma unroll
        for (int kk = 0; kk < 16; kk++) {
            float ar[8], br[8];
            *(float4*)&ar[0] = *(const float4*)&As[kk][ty * 8];
            *(float4*)&ar[4] = *(const float4*)&As[kk][ty * 8 + 4];
            *(float4*)&br[0] = *(const float4*)&Bs[kk][tx * 8];
            *(float4*)&br[4] = *(const float4*)&Bs[kk][tx * 8 + 4];
            #pragma unroll
            for (int i = 0; i < 8; i++)
                #pragma unroll
                for (int j = 0; j < 8; j++)
                    acc[i][j] += ar[i] * br[j];
        }
        __syncthreads();
    }

    float* dst = (bx < 2) ? g_feat : g_pos;
    const int col0 = ((bx < 2) ? bx : (bx - 2)) * 128 + tx * 8;
    float bi[8];
    *(float4*)&bi[0] = *(const float4*)(bias + bx * 128 + tx * 8);
    *(float4*)&bi[4] = *(const float4*)(bias + bx * 128 + tx * 8 + 4);

    #pragma unroll
    for (int i = 0; i < 8; i++) {
        int r = by * 128 + ty * 8 + i;
        float4 v0, v1;
        v0.x = acc[i][0] + bi[0]; v0.y = acc[i][1] + bi[1];
        v0.z = acc[i][2] + bi[2]; v0.w = acc[i][3] + bi[3];
        v1.x = acc[i][4] + bi[4]; v1.y = acc[i][5] + bi[5];
        v1.z = acc[i][6] + bi[6]; v1.w = acc[i][7] + bi[7];
        *(float4*)(dst + (size_t)r * CC + col0)     = v0;
        *(float4*)(dst + (size_t)r * CC + col0 + 4) = v1;
    }
}

// ===========================================================================
// Normalize pos rows, then 3-way bf16 split: p = hi + mid + lo
// ===========================================================================
__global__ __launch_bounds__(256) void norm_split_kernel()
{
    const int row = blockIdx.x;
    const int tid = threadIdx.x;
    float v = g_pos[(size_t)row * CC + tid];
    float s = v * v;
    #pragma unroll
    for (int o = 16; o; o >>= 1) s += __shfl_down_sync(0xffffffffu, s, o);
    __shared__ float red[8];
    if ((tid & 31) == 0) red[tid >> 5] = s;
    __syncthreads();
    float total = red[0] + red[1] + red[2] + red[3] + red[4] + red[5] + red[6] + red[7];
    float scale = 1.0f / fmaxf(sqrtf(total), 1e-12f);
    float p = v * scale;

    __nv_bfloat16 hi = __float2bfloat16_rn(p);
    float r1 = p - __bfloat162float(hi);
    __nv_bfloat16 mid = __float2bfloat16_rn(r1);
    float r2 = r1 - __bfloat162float(mid);
    __nv_bfloat16 lo = __float2bfloat16_rn(r2);

    size_t off = (size_t)row * CC + tid;
    g_hi [off] = hi;
    g_mid[off] = mid;
    g_lo [off] = lo;
}

// ===========================================================================
// GEMM2 on HMMA (mma.sync bf16): sim = P @ P^T via expanded K = 6*256 = 1536
// (3-way split: hh, hm, mh, mm, hl, lh). 128x128 tile, cp.async double buffer,
// symmetric (by<=bx) with mirror store via smem transpose.
// ===========================================================================
#define G2_TILE   16384                      // 128 rows x 64 bf16 (swizzled)
#define G2_CHUNK  (2 * G2_TILE)              // A + B = 32KB
#define G2_SMEM   (2 * G2_CHUNK)             // double buffered = 64KB

__global__ __launch_bounds__(256) void gemm2_mma_kernel()
{
    extern __shared__ char dsm[];

    const int b = blockIdx.y;
    // triangular decode: t -> (by, bx), by <= bx, NT = 32
    const int NT = NN / 128;
    const int t = blockIdx.x;
    float ffq = (float)((2 * NT + 1) * (2 * NT + 1)) - 8.0f * (float)t;
    int by = (int)floorf(((float)(2 * NT + 1) - sqrtf(ffq)) * 0.5f);
    while ((by + 1) * NT - ((by + 1) * by) / 2 <= t) by++;
    while (by * NT - (by * (by - 1)) / 2 > t) by--;
    const int bx = by + (t - (by * NT - (by * (by - 1)) / 2));

    const int tid = threadIdx.x;
    const int wid = tid >> 5, lane = tid & 31;
    const int wm = wid >> 2, wn = wid & 3;   // warp grid 2 x 4 (64x32 tiles)

    const size_t baseA = ((size_t)b * NN + (size_t)by * 128) * CC;
    const size_t baseB = ((size_t)b * NN + (size_t)bx * 128) * CC;
    const __nv_bfloat16* srcsA[3] = { g_hi + baseA, g_mid + baseA, g_lo + baseA };
    const __nv_bfloat16* srcsB[3] = { g_hi + baseB, g_mid + baseB, g_lo + baseB };
    const int segA[6] = {0, 0, 1, 1, 0, 2};
    const int segB[6] = {0, 1, 0, 1, 2, 0};

    // per-thread copy coords (8 x 16B per chunk: 4 for A, 4 for B)
    const int cpRow = tid >> 1;                  // reused with +128 offset trick
    (void)cpRow;

    float acc[4][4][4] = {};

    // ---- chunk loader (c: 0..23) ----
    auto issue_chunk = [&](int c) {
        const int seg = c >> 2;
        const int kc = (c & 3) * 64;
        const __nv_bfloat16* sA = srcsA[segA[seg]];
        const __nv_bfloat16* sB = srcsB[segB[seg]];
        char* bufA = dsm + (c & 1) * G2_CHUNK;
        char* bufB = bufA + G2_TILE;
        uint32_t sa = smem_u32(bufA), sb = smem_u32(bufB);
        #pragma unroll
        for (int it = 0; it < 4; it++) {
            int u = tid + it * 256;              // 0..1023
            int row = u >> 3, seg16 = u & 7;
            uint32_t dsw = SMEM_SWIZZLE_128B((uint32_t)(row * 128 + seg16 * 16));
            cp_async16(sa + dsw, sA + (size_t)row * CC + kc + seg16 * 8);
            cp_async16(sb + dsw, sB + (size_t)row * CC + kc + seg16 * 8);
        }
        CP_COMMIT();
    };

    issue_chunk(0);

    // ldmatrix lane address components
    const int rowA_l = wm * 64 + (lane & 15);
    const int kkA_l  = (lane >> 4) * 8;
    const int nB_l   = wn * 32 + (lane & 7) + (lane >> 4) * 8;
    const int kkB_l  = ((lane >> 3) & 1) * 8;

    for (int c = 0; c < 24; c++) {
        if (c + 1 < 24) { issue_chunk(c + 1); CP_WAIT(1); }
        else            { CP_WAIT(0); }
        __syncthreads();

        uint32_t sa = smem_u32(dsm + (c & 1) * G2_CHUNK);
        uint32_t sb = sa + G2_TILE;

        #pragma unroll
        for (int k0 = 0; k0 < 64; k0 += 16) {
            uint32_t afr[4][4], bfr[2][4];
            #pragma unroll
            for (int mt = 0; mt < 4; mt++) {
                uint32_t byte = (uint32_t)((rowA_l + mt * 16) * 128 + (k0 + kkA_l) * 2);
                ldm_x4(afr[mt], sa + SMEM_SWIZZLE_128B(byte));
            }
            #pragma unroll
            for (int np = 0; np < 2; np++) {
                uint32_t byte = (uint32_t)((nB_l + np * 16) * 128 + (k0 + kkB_l) * 2);
                ldm_x4(bfr[np], sb + SMEM_SWIZZLE_128B(byte));
            }
            #pragma unroll
            for (int mt = 0; mt < 4; mt++)
                #pragma unroll
                for (int nt = 0; nt < 4; nt++)
                    mma_bf16(acc[mt][nt], afr[mt],
                             bfr[nt >> 1][(nt & 1) * 2], bfr[nt >> 1][(nt & 1) * 2 + 1]);
        }
        __syncthreads();
    }

    // ---- epilogue: stage through smem (two 64-col halves), coalesced stores
    float* sbuf = (float*)dsm;                   // 128 x 68 pitch = 34816 B
    float* __restrict__ S = g_sim + (size_t)b * NN * NN;
    const int row0 = by * 128, col0 = bx * 128;

    for (int h = 0; h < 2; h++) {
        if ((wn >> 1) == h) {
            const int cbase = (wn & 1) * 32;
            #pragma unroll
            for (int mt = 0; mt < 4; mt++) {
                int r = wm * 64 + mt * 16 + (lane >> 2);
                #pragma unroll
                for (int nt = 0; nt < 4; nt++) {
                    int cl = cbase + nt * 8 + 2 * (lane & 3);
                    *(float2*)&sbuf[r * 68 + cl]       = make_float2(acc[mt][nt][0], acc[mt][nt][1]);
                    *(float2*)&sbuf[(r + 8) * 68 + cl] = make_float2(acc[mt][nt][2], acc[mt][nt][3]);
                }
            }
        }
        __syncthreads();
        // direct (coalesced rows)
        for (int idx = tid; idx < 128 * 16; idx += 256) {
            int r = idx >> 4, c4 = (idx & 15) * 4;
            float4 v = *(float4*)&sbuf[r * 68 + c4];
            *(float4*)(S + (size_t)(row0 + r) * NN + col0 + h * 64 + c4) = v;
        }
        // mirror (transposed)
        if (bx != by) {
            for (int idx = tid; idx < 64 * 32; idx += 256) {
                int cI = idx & 63, r4 = (idx >> 6) * 4;
                float4 v;
                v.x = sbuf[(r4 + 0) * 68 + cI];
                v.y = sbuf[(r4 + 1) * 68 + cI];
                v.z = sbuf[(r4 + 2) * 68 + cI];
                v.w = sbuf[(r4 + 3) * 68 + cI];
                *(float4*)(S + (size_t)(col0 + h * 64 + cI) * NN + row0 + r4) = v;
            }
        }
        __syncthreads();
    }
}

// ===========================================================================
// top-32 + softmax + gather: ONE WARP PER ROW, streaming exact top-k.
// ===========================================================================
static __device__ __forceinline__ unsigned f2key(float f) {
    unsigned u = __float_as_uint(f);
    return u ^ (0x80000000u | (unsigned)((int)u >> 31));
}
static __device__ __forceinline__ float key2f(unsigned k) {
    unsigned u = (k & 0x80000000u) ? (k ^ 0x80000000u) : ~k;
    return __uint_as_float(u);
}

__global__ __launch_bounds__(256) void topk_warp_kernel(float* __restrict__ out)
{
    const unsigned FULL = 0xffffffffu;
    const int wrow = blockIdx.x * 8 + (threadIdx.x >> 5);
    const int lane = threadIdx.x & 31;
    const int b = wrow >> 12;
    const float* __restrict__ srow = g_sim + (size_t)wrow * NN;

    float4 f = *(const float4*)(srow + lane * 4);
    unsigned skey = f2key(f.x);
    int sidx = lane * 4;
    unsigned curmin = __reduce_min_sync(FULL, skey);
    int minlane = __ffs(__ballot_sync(FULL, skey == curmin)) - 1;

    float4 fn;
    for (int j = 0; j < 32; j++) {
        if (j + 1 < 32) fn = *(const float4*)(srow + (j + 1) * 128 + lane * 4);
        float fv[4] = { f.x, f.y, f.z, f.w };
        #pragma unroll
        for (int q = 0; q < 4; q++) {
            if (j == 0 && q == 0) continue;
            unsigned key = f2key(fv[q]);
            unsigned m = __ballot_sync(FULL, key > curmin);
            while (m) {
                int src = __ffs(m) - 1;
                m &= m - 1;
                unsigned k2 = __shfl_sync(FULL, key, src);
                if (k2 > curmin) {
                    int i2 = j * 128 + src * 4 + q;
                    if (lane == minlane) { skey = k2; sidx = i2; }
                    curmin = __reduce_min_sync(FULL, skey);
                    minlane = __ffs(__ballot_sync(FULL, skey == curmin)) - 1;
                }
            }
        }
        f = fn;
    }

    unsigned kmax = __reduce_max_sync(FULL, skey);
    float vmax = key2f(kmax);
    float v = key2f(skey);
    float a = expf(v - vmax);
    float ssum = a;
    #pragma unroll
    for (int o = 16; o; o >>= 1) ssum += __shfl_xor_sync(FULL, ssum, o);
    float wgt = a / ssum;

    const float* __restrict__ fbase = g_feat + (size_t)b * NN * CC;
    float4 acc0 = {0.f, 0.f, 0.f, 0.f}, acc1 = {0.f, 0.f, 0.f, 0.f};
    #pragma unroll 4
    for (int k = 0; k < KK; k++) {
        int id = __shfl_sync(FULL, sidx, k);
        float wk = __shfl_sync(FULL, wgt, k);
        const float* fr = fbase + (size_t)id * CC;
        float4 f0 = *(const float4*)(fr + lane * 4);
        float4 f1 = *(const float4*)(fr + 128 + lane * 4);
        acc0.x += wk * f0.x; acc0.y += wk * f0.y;
        acc0.z += wk * f0.z; acc0.w += wk * f0.w;
        acc1.x += wk * f1.x; acc1.y += wk * f1.y;
        acc1.z += wk * f1.z; acc1.w += wk * f1.w;
    }
    *(float4*)(out + (size_t)wrow * CC + lane * 4)       = acc0;
    *(float4*)(out + (size_t)wrow * CC + 128 + lane * 4) = acc1;
}

// ===========================================================================
extern "C" void kernel_launch(void* const* d_in, const int* in_sizes, int n_in,
                              void* d_out, int out_size)
{
    const float* x    = (const float*)d_in[0];
    const float* W    = (const float*)d_in[1];
    const float* bias = (const float*)d_in[2];
    float* out = (float*)d_out;

    cudaFuncSetAttribute(gemm2_mma_kernel,
                         cudaFuncAttributeMaxDynamicSharedMemorySize, G2_SMEM);

    dim3 g1(DD / 128, (BB * NN) / 128);
    gemm1_kernel<<<g1, 256>>>(x, W, bias);

    norm_split_kernel<<<BB * NN, 256>>>();

    const int NT = NN / 128;
    dim3 g2(NT * (NT + 1) / 2, BB);
    gemm2_mma_kernel<<<g2, 256, G2_SMEM>>>();

    topk_warp_kernel<<<(BB * NN) / 8, 256>>>(out);
}